// round 12
// baseline (speedup 1.0000x reference)
#include <cuda_runtime.h>
#include <cuda_bf16.h>
#include <math.h>
#include <stdint.h>

#define TT 512
#define BB 64
#define HH 1024
#define GG 4096
#define NCTA 128

#if defined(__CUDA_ARCH__) && (defined(__CUDA_ARCH_FEAT_SM103_ALL) || \
    defined(__CUDA_ARCH_FEAT_SM100_ALL) || \
    (defined(__CUDA_ARCH_FAMILY_SPECIFIC__) && __CUDA_ARCH_FAMILY_SPECIFIC__ >= 1000))
#define TC_OK 1
#else
#define TC_OK 0
#endif

// ---------------- device globals ----------------
__device__ __align__(16) float g_xproj[(size_t)TT * BB * GG];      // 512 MB
// pre-swizzled chunk-major tiles: [tile][chunk][16 KB = 128 rows x 128 B SW128]
__device__ __align__(128) char g_xA2[512][16][16384];              // 128 MB
__device__ __align__(128) char g_whi2[32][16][16384];              // 8 MB
__device__ __align__(128) char g_wlo2[32][16][16384];              // 8 MB
__device__ __align__(128) char g_hsplit2[2][16][16384];            // h dbl buf
__device__ __align__(16) float g_h[2][BB * HH];                    // SIMT fallback
__device__ unsigned g_bar_count = 0, g_bar_gen = 0;
__device__ unsigned g_ck[2][16];                                   // chunk-ready counters

__device__ __forceinline__ float sigf(float x) { return 1.f / (1.f + __expf(-x)); }
__device__ __forceinline__ void split2(float a, float b, unsigned& hu, unsigned& lu) {
    __nv_bfloat16 h0 = __float2bfloat16(a), h1 = __float2bfloat16(b);
    float l0 = a - __bfloat162float(h0), l1 = b - __bfloat162float(h1);
    hu = (unsigned)__bfloat16_as_ushort(h0) | ((unsigned)__bfloat16_as_ushort(h1) << 16);
    lu = (unsigned)__bfloat16_as_ushort(__float2bfloat16(l0)) |
         ((unsigned)__bfloat16_as_ushort(__float2bfloat16(l1)) << 16);
}
__device__ __forceinline__ void grid_barrier() {
    __threadfence();
    __syncthreads();
    if (threadIdx.x == 0) {
        unsigned target = *(volatile unsigned*)&g_bar_gen + 1u;
        unsigned old = atomicAdd(&g_bar_count, 1u);
        if (old == NCTA - 1u) { g_bar_count = 0u; __threadfence(); atomicExch(&g_bar_gen, target); }
        else { while ((int)(*(volatile unsigned*)&g_bar_gen - target) < 0) __nanosleep(32); }
        __threadfence();
    }
    __syncthreads();
}

// ---------------- PTX helpers ----------------
__device__ __forceinline__ uint32_t smem_u32(const void* p) {
    uint32_t a;
    asm("{ .reg .u64 t; cvta.to.shared.u64 t, %1; cvt.u32.u64 %0, t; }" : "=r"(a) : "l"(p));
    return a;
}
#define SWZ(o) ((o) ^ ((((uint32_t)(o)) >> 3) & 0x70))
__device__ __forceinline__ uint64_t make_desc(uint32_t a) {
    return ((2ull << 61) | (1ull << 46) | (64ull << 32) | (1ull << 16)) | (uint64_t)((a >> 4) & 0x3FFF);
}
__device__ __forceinline__ void mbar_init(uint32_t a, uint32_t n) {
    asm volatile("mbarrier.init.shared.b64 [%0], %1;" :: "r"(a), "r"(n) : "memory");
}
__device__ __forceinline__ void mbar_wait(uint32_t a, uint32_t ph) {
    asm volatile("{\n .reg .pred P;\nWL_%=:\n"
                 " mbarrier.try_wait.parity.acquire.cta.shared::cta.b64 P, [%0], %1, 0x989680;\n"
                 " @P bra WD_%=;\n bra WL_%=;\nWD_%=:\n}" :: "r"(a), "r"(ph) : "memory");
}
__device__ __forceinline__ void mbar_expect_tx(uint32_t a, uint32_t bytes) {
    asm volatile("mbarrier.arrive.expect_tx.shared.b64 _, [%0], %1;" :: "r"(a), "r"(bytes) : "memory");
}
__device__ __forceinline__ void bulk_g2s(uint32_t dst, const void* src, uint32_t bytes, uint32_t mbar) {
    asm volatile("cp.async.bulk.shared::cta.global.mbarrier::complete_tx::bytes [%0], [%1], %2, [%3];"
                 :: "r"(dst), "l"(src), "r"(bytes), "r"(mbar) : "memory");
}
#if TC_OK
__device__ __forceinline__ void mma_ss(uint32_t d, uint64_t ad, uint64_t bd, uint32_t idesc, uint32_t acc) {
    asm volatile("{\n .reg .pred p;\n setp.ne.u32 p, %5, 0;\n"
                 " tcgen05.mma.cta_group::1.kind::f16 [%0], %1, %2, %3, {%4,%4,%4,%4}, p;\n}"
                 :: "r"(d), "l"(ad), "l"(bd), "r"(idesc), "r"(0u), "r"(acc) : "memory");
}
__device__ __forceinline__ void tc_commit(uint32_t m) {
    asm volatile("tcgen05.commit.cta_group::1.mbarrier::arrive::one.shared::cluster.b64 [%0];" :: "r"(m) : "memory");
}
#define TC_ALLOC(slot, n)  asm volatile("tcgen05.alloc.cta_group::1.sync.aligned.shared::cta.b32 [%0], %1;" :: "r"(slot), "r"(n) : "memory")
#define TC_DEALLOC(t, n)   asm volatile("tcgen05.dealloc.cta_group::1.sync.aligned.b32 %0, %1;" :: "r"(t), "r"(n))
#define TC_RELINQ()        asm volatile("tcgen05.relinquish_alloc_permit.cta_group::1.sync.aligned;")
#define TC_FENCE_AFTER()   asm volatile("tcgen05.fence::after_thread_sync;" ::: "memory")
#define TC_WAIT_LD()       asm volatile("tcgen05.wait::ld.sync.aligned;" ::: "memory")
#define FENCE_ASYNC()      asm volatile("fence.proxy.async.shared::cta;" ::: "memory")
#define LDTM_X32(r, a) \
    asm volatile("tcgen05.ld.sync.aligned.32x32b.x32.b32 " \
        "{%0,%1,%2,%3,%4,%5,%6,%7,%8,%9,%10,%11,%12,%13,%14,%15," \
        "%16,%17,%18,%19,%20,%21,%22,%23,%24,%25,%26,%27,%28,%29,%30,%31}, [%32];" \
        : "=r"((r)[0]),"=r"((r)[1]),"=r"((r)[2]),"=r"((r)[3]),"=r"((r)[4]),"=r"((r)[5]),"=r"((r)[6]),"=r"((r)[7]), \
          "=r"((r)[8]),"=r"((r)[9]),"=r"((r)[10]),"=r"((r)[11]),"=r"((r)[12]),"=r"((r)[13]),"=r"((r)[14]),"=r"((r)[15]), \
          "=r"((r)[16]),"=r"((r)[17]),"=r"((r)[18]),"=r"((r)[19]),"=r"((r)[20]),"=r"((r)[21]),"=r"((r)[22]),"=r"((r)[23]), \
          "=r"((r)[24]),"=r"((r)[25]),"=r"((r)[26]),"=r"((r)[27]),"=r"((r)[28]),"=r"((r)[29]),"=r"((r)[30]),"=r"((r)[31]) \
        : "r"(a))
#endif

#define IDESC_N32  0x8080490u   // f32 acc, bf16 x bf16, K-major, M=128, N=32
#define IDESC_N128 0x8200490u   // same, N=128

// ---------------- conversion kernels (pre-swizzled chunk-major) ----------------
__global__ __launch_bounds__(256) void conv_x(const float* __restrict__ x) {
#if TC_OK
    size_t e = ((size_t)blockIdx.x * 256 + threadIdx.x) * 4;
    int m = (int)(e >> 10), k = (int)(e & 1023);
    float4 v = *reinterpret_cast<const float4*>(x + e);
    uint2 hu, lu;
    split2(v.x, v.y, hu.x, lu.x);
    split2(v.z, v.w, hu.y, lu.y);
    int mt = m >> 6, b = m & 63, c = k >> 6, kk = k & 63;
    *reinterpret_cast<uint2*>(&g_xA2[mt][c][SWZ((uint32_t)(b * 128 + kk * 2))])        = hu;
    *reinterpret_cast<uint2*>(&g_xA2[mt][c][SWZ((uint32_t)((64 + b) * 128 + kk * 2))]) = lu;
#endif
}
__global__ __launch_bounds__(256) void conv_w(const float* __restrict__ W) {
#if TC_OK
    size_t e = ((size_t)blockIdx.x * 256 + threadIdx.x) * 4;
    int m = (int)(e >> 10), k = (int)(e & 1023);
    float4 v = *reinterpret_cast<const float4*>(W + e);
    uint2 hu, lu;
    split2(v.x, v.y, hu.x, lu.x);
    split2(v.z, v.w, hu.y, lu.y);
    int nt = m >> 7, row = m & 127, c = k >> 6, kk = k & 63;
    uint32_t off = SWZ((uint32_t)(row * 128 + kk * 2));
    *reinterpret_cast<uint2*>(&g_whi2[nt][c][off]) = hu;
    *reinterpret_cast<uint2*>(&g_wlo2[nt][c][off]) = lu;
#endif
}

// ---------------- xproj: bulk dual-driver tcgen05 GEMM ----------------
// buf i (i<2): A @ i*49152, Bhi @ +16384, Blo @ +32768
#define X_RED  98304
#define X_BIAS 106752
#define X_MISC 107264   // tmem@0; mma mbars@16,24; load mbars@32,40; fin@48
#define X_SMEM 107328

__global__ __launch_bounds__(256, 2) void xproj_tc(const float* __restrict__ bih,
                                                   const float* __restrict__ bhh) {
#if TC_OK
    extern __shared__ __align__(16) char sm[];
    const uint32_t sb = smem_u32(sm);
    const int tid = threadIdx.x, wid = tid >> 5, lane = tid & 31;
    const int nt = blockIdx.x, mt = blockIdx.y;
    float* Red  = reinterpret_cast<float*>(sm + X_RED);
    float* Bias = reinterpret_cast<float*>(sm + X_BIAS);
    const uint32_t mb_mma  = sb + X_MISC + 16;
    const uint32_t mb_load = sb + X_MISC + 32;
    const uint32_t mb_fin  = sb + X_MISC + 48;

    if (wid == 0) { TC_ALLOC(sb + X_MISC, 128); TC_RELINQ(); }
    if (tid < 128) Bias[tid] = bih[nt * 128 + tid] + bhh[nt * 128 + tid];
    if (tid == 0) {
        mbar_init(mb_mma, 1);  mbar_init(mb_mma + 8, 1);
        mbar_init(mb_load, 1); mbar_init(mb_load + 8, 1);
        mbar_init(mb_fin, 1);
    }
    __syncthreads();
    uint32_t tmem;
    asm volatile("ld.shared.b32 %0, [%1];" : "=r"(tmem) : "r"(sb + X_MISC));

    if (tid == 128) {             // load driver
        int phm[2] = {0, 0};
        for (int c = 0; c < 16; c++) {
            const int buf = c & 1;
            if (c >= 2) { mbar_wait(mb_mma + buf * 8, phm[buf]); phm[buf] ^= 1; }
            mbar_expect_tx(mb_load + buf * 8, 49152);
            uint32_t d = sb + (uint32_t)buf * 49152;
            bulk_g2s(d,         g_xA2[mt][c],  16384, mb_load + buf * 8);
            bulk_g2s(d + 16384, g_whi2[nt][c], 16384, mb_load + buf * 8);
            bulk_g2s(d + 32768, g_wlo2[nt][c], 16384, mb_load + buf * 8);
        }
    } else if (tid == 0) {        // MMA driver
        int phl[2] = {0, 0};
        for (int c = 0; c < 16; c++) {
            const int buf = c & 1;
            mbar_wait(mb_load + buf * 8, phl[buf]); phl[buf] ^= 1;
            uint32_t d = sb + (uint32_t)buf * 49152;
            uint64_t ad = make_desc(d), dh = make_desc(d + 16384), dl = make_desc(d + 32768);
#pragma unroll
            for (int ks = 0; ks < 4; ks++) {
                mma_ss(tmem, ad + 2 * ks, dh + 2 * ks, IDESC_N128, !(c == 0 && ks == 0));
                mma_ss(tmem, ad + 2 * ks, dl + 2 * ks, IDESC_N128, 1);
            }
            tc_commit(mb_mma + buf * 8);
        }
        tc_commit(mb_fin);        // tracks ALL prior MMAs of this thread
        mbar_wait(mb_fin, 0);     // properly paced: single flip
    }
    __syncthreads();
    TC_FENCE_AFTER();

    for (int blk = 0; blk < 4; blk++) {
        uint32_t rr[32];
        if (wid < 4) {
            LDTM_X32(rr, tmem + blk * 32);
            TC_WAIT_LD();
            if (wid >= 2) {
                int b = (wid - 2) * 32 + lane;
#pragma unroll
                for (int c = 0; c < 32; c++) Red[b * 33 + c] = __uint_as_float(rr[c]);
            }
        }
        __syncthreads();
        if (wid < 2) {
            int b = wid * 32 + lane;
            float* dst = &g_xproj[(size_t)(mt * 64 + b) * GG + nt * 128 + blk * 32];
#pragma unroll
            for (int c = 0; c < 32; c += 4) {
                float4 v = make_float4(
                    __uint_as_float(rr[c + 0]) + Red[b * 33 + c + 0] + Bias[blk * 32 + c + 0],
                    __uint_as_float(rr[c + 1]) + Red[b * 33 + c + 1] + Bias[blk * 32 + c + 1],
                    __uint_as_float(rr[c + 2]) + Red[b * 33 + c + 2] + Bias[blk * 32 + c + 2],
                    __uint_as_float(rr[c + 3]) + Red[b * 33 + c + 3] + Bias[blk * 32 + c + 3]);
                *reinterpret_cast<float4*>(dst + c) = v;
            }
        }
        __syncthreads();
    }
    if (wid == 0) TC_DEALLOC(tmem, 128);
#endif
}

// ---------------- persistent recurrence: counter-gated free-running pipeline ----
#define P_WHI  0                 // 65536
#define P_WLO  65536             // 65536
#define P_ABUF 131072            // 4 x 16384
#define P_RED  196608            // 8448
#define P_MISC 205056            // tmem@0; mma@16+8i; load@48+8i; fin@80
#define P_SMEM 205152

__global__ __launch_bounds__(256) void lstm_persist_tc(const float* __restrict__ Whh,
                                                       float* __restrict__ out) {
#if TC_OK
    extern __shared__ __align__(16) char sm[];
    const uint32_t sb = smem_u32(sm);
    const int tid = threadIdx.x, wid = tid >> 5, lane = tid & 31;
    const int bk = blockIdx.x;
    float* Red = reinterpret_cast<float*>(sm + P_RED);
    const uint32_t mb_mma  = sb + P_MISC + 16;
    const uint32_t mb_load = sb + P_MISC + 48;
    const uint32_t mb_fin  = sb + P_MISC + 80;

    // W_hh slice -> SMEM SW128 (hi/lo)
    for (int i = tid; i < 8192; i += 256) {
        int e = i * 4, cc = e >> 10, k = e & 1023;
        float4 v = *reinterpret_cast<const float4*>(
            &Whh[(size_t)((cc >> 3) * HH + bk * 8 + (cc & 7)) * HH + k]);
        uint2 hu, lu;
        split2(v.x, v.y, hu.x, lu.x);
        split2(v.z, v.w, hu.y, lu.y);
        uint32_t off = (uint32_t)((k >> 6) * 4096 + (cc >> 3) * 1024 + (cc & 7) * 128 + (k & 63) * 2);
        *reinterpret_cast<uint2*>(sm + P_WHI + SWZ(off)) = hu;
        *reinterpret_cast<uint2*>(sm + P_WLO + SWZ(off)) = lu;
    }
    if (tid < 128) {
        *reinterpret_cast<uint4*>(
            &g_hsplit2[0][bk >> 3][SWZ((uint32_t)tid * 128 + (bk & 7) * 16)]) =
            make_uint4(0, 0, 0, 0);
    }
    if (bk == 0 && tid < 32) reinterpret_cast<unsigned*>(g_ck)[tid] = 0;
    if (wid == 0) { TC_ALLOC(sb + P_MISC, 32); TC_RELINQ(); }
    if (tid == 0) {
#pragma unroll
        for (int i = 0; i < 4; i++) { mbar_init(mb_mma + i * 8, 1); mbar_init(mb_load + i * 8, 1); }
        mbar_init(mb_fin, 1);
    }
    __syncthreads();
    FENCE_ASYNC();   // generic W stores -> async-proxy MMA reads
    uint32_t tmem;
    asm volatile("ld.shared.b32 %0, [%1];" : "=r"(tmem) : "r"(sb + P_MISC));
    grid_barrier();  // h0 zeros + counters reset visible everywhere

    if (tid == 128) {
        // ---------------- load driver: free-running, counter-gated ----------------
        int phm[4] = {0, 0, 0, 0};
        for (int t = 0; t < TT; ++t) {
            const char* asrc = g_hsplit2[t & 1][0];
            const unsigned need = 8u * ((unsigned)(t + (t & 1)) >> 1);
            for (int c = 0; c < 16; c++) {
                const int buf = c & 3;
                if (t > 0 || c >= 4) { mbar_wait(mb_mma + buf * 8, phm[buf]); phm[buf] ^= 1; }
                if (t > 0) {
                    while (*(volatile unsigned*)&g_ck[t & 1][c] < need) {}
                    __threadfence();
                }
                mbar_expect_tx(mb_load + buf * 8, 16384);
                bulk_g2s(sb + P_ABUF + buf * 16384, asrc + c * 16384, 16384, mb_load + buf * 8);
            }
        }
    } else if (wid < 4) {
        // ---------------- compute warps (0-3) ----------------
        int phl[4] = {0, 0, 0, 0};
        int phf = 0;
        float cr[8];
#pragma unroll
        for (int j = 0; j < 8; j++) cr[j] = 0.f;

        for (int t = 0; t < TT; ++t) {
            float4 xpr[8];
            if (wid < 2) {
                int b = wid * 32 + lane;
                const float* xsrc = &g_xproj[((size_t)t * BB + b) * GG + bk * 8];
#pragma unroll
                for (int g = 0; g < 4; g++) {
                    xpr[2 * g]     = *reinterpret_cast<const float4*>(xsrc + g * HH);
                    xpr[2 * g + 1] = *reinterpret_cast<const float4*>(xsrc + g * HH + 4);
                }
            }
            if (tid == 0) {
#pragma unroll
                for (int c = 0; c < 16; c++) {
                    const int buf = c & 3;
                    mbar_wait(mb_load + buf * 8, phl[buf]); phl[buf] ^= 1;
                    uint64_t ad = make_desc(sb + P_ABUF + buf * 16384);
                    uint64_t dh = make_desc(sb + P_WHI + c * 4096);
                    uint64_t dl = make_desc(sb + P_WLO + c * 4096);
#pragma unroll
                    for (int ks = 0; ks < 4; ks++) {
                        mma_ss(tmem, ad + 2 * ks, dh + 2 * ks, IDESC_N32, !(c == 0 && ks == 0));
                        mma_ss(tmem, ad + 2 * ks, dl + 2 * ks, IDESC_N32, 1);
                    }
                    tc_commit(mb_mma + buf * 8);
                }
                tc_commit(mb_fin);
                mbar_wait(mb_fin, phf); phf ^= 1;   // paced: 1 flip/step
            }
            asm volatile("bar.sync 2, 128;" ::: "memory");
            TC_FENCE_AFTER();

            uint32_t rr[32];
            LDTM_X32(rr, tmem);
            TC_WAIT_LD();
            if (wid >= 2) {
                int b = (wid - 2) * 32 + lane;
#pragma unroll
                for (int c = 0; c < 32; c++) Red[b * 33 + c] = __uint_as_float(rr[c]);
            }
            asm volatile("bar.sync 2, 128;" ::: "memory");
            if (wid < 2) {
                int b = wid * 32 + lane;
                const float* xpf = reinterpret_cast<const float*>(xpr);
                float gate[32];
#pragma unroll
                for (int c = 0; c < 32; c++)
                    gate[c] = xpf[c] + __uint_as_float(rr[c]) + Red[b * 33 + c];

                float hs[8];
                __nv_bfloat16 hb[8], lb[8];
#pragma unroll
                for (int j = 0; j < 8; j++) {
                    float iv = sigf(gate[j]);
                    float fv = sigf(gate[8 + j]);
                    float gv = tanhf(gate[16 + j]);
                    float ov = sigf(gate[24 + j]);
                    cr[j] = fv * cr[j] + iv * gv;
                    hs[j] = ov * tanhf(cr[j]);
                    hb[j] = __float2bfloat16(hs[j]);
                    lb[j] = __float2bfloat16(hs[j] - __bfloat162float(hb[j]));
                }
                float* op = &out[((size_t)t * BB + b) * HH + bk * 8];
                *reinterpret_cast<float4*>(op)     = make_float4(hs[0], hs[1], hs[2], hs[3]);
                *reinterpret_cast<float4*>(op + 4) = make_float4(hs[4], hs[5], hs[6], hs[7]);
                const int nsel = (t + 1) & 1;
                char* hcb = g_hsplit2[nsel][bk >> 3];
                *reinterpret_cast<uint4*>(&hcb[SWZ((uint32_t)b * 128 + (bk & 7) * 16)]) =
                    *reinterpret_cast<uint4*>(hb);
                *reinterpret_cast<uint4*>(&hcb[SWZ((uint32_t)(64 + b) * 128 + (bk & 7) * 16)]) =
                    *reinterpret_cast<uint4*>(lb);
                if (t == TT - 1) {
                    float* hp = &out[(size_t)TT * BB * HH + (size_t)b * HH + bk * 8];
                    *reinterpret_cast<float4*>(hp)     = make_float4(hs[0], hs[1], hs[2], hs[3]);
                    *reinterpret_cast<float4*>(hp + 4) = make_float4(hs[4], hs[5], hs[6], hs[7]);
                    float* cp = hp + (size_t)BB * HH;
                    *reinterpret_cast<float4*>(cp)     = make_float4(cr[0], cr[1], cr[2], cr[3]);
                    *reinterpret_cast<float4*>(cp + 4) = make_float4(cr[4], cr[5], cr[6], cr[7]);
                }
                // publish: this CTA's h slice for step t+1 is in gmem
                asm volatile("bar.sync 1, 64;" ::: "memory");
                if (tid == 0) {
                    __threadfence();
                    atomicAdd(&g_ck[nsel][bk >> 3], 1u);
                }
            }
        }
    }
    __syncthreads();
    if (wid == 0) TC_DEALLOC(tmem, 32);
#endif
}

// ---------------- SIMT fallback (non-'a' pass only) ----------------
#define XAS 68
__global__ __launch_bounds__(256) void xproj_simt(
    const float* __restrict__ x, const float* __restrict__ Wih,
    const float* __restrict__ bih, const float* __restrict__ bhh)
{
#if !TC_OK
    __shared__ __align__(16) float As[32 * XAS];
    __shared__ __align__(16) float Bs[32 * XAS];
    const int tid = threadIdx.x;
    const int n0 = blockIdx.x * 64, m0 = blockIdx.y * 64;
    const int ty = tid >> 4, tx = tid & 15;
    const float* Ab = x   + (size_t)m0 * HH;
    const float* Bb = Wih + (size_t)n0 * HH;
    float acc[4][4];
#pragma unroll
    for (int i = 0; i < 4; i++)
#pragma unroll
        for (int j = 0; j < 4; j++) acc[i][j] = 0.f;
    float4 ra[2], rb[2];
#pragma unroll
    for (int i = 0; i < 2; i++) {
        int s = tid + i * 256; int r = s >> 3, cc = s & 7;
        ra[i] = *reinterpret_cast<const float4*>(Ab + (size_t)r * HH + cc * 4);
        rb[i] = *reinterpret_cast<const float4*>(Bb + (size_t)r * HH + cc * 4);
    }
    for (int k0 = 0; k0 < HH; k0 += 32) {
        __syncthreads();
#pragma unroll
        for (int i = 0; i < 2; i++) {
            int s = tid + i * 256; int r = s >> 3, cc = s & 7;
            As[(cc * 4 + 0) * XAS + r] = ra[i].x; As[(cc * 4 + 1) * XAS + r] = ra[i].y;
            As[(cc * 4 + 2) * XAS + r] = ra[i].z; As[(cc * 4 + 3) * XAS + r] = ra[i].w;
            Bs[(cc * 4 + 0) * XAS + r] = rb[i].x; Bs[(cc * 4 + 1) * XAS + r] = rb[i].y;
            Bs[(cc * 4 + 2) * XAS + r] = rb[i].z; Bs[(cc * 4 + 3) * XAS + r] = rb[i].w;
        }
        __syncthreads();
        if (k0 + 32 < HH) {
#pragma unroll
            for (int i = 0; i < 2; i++) {
                int s = tid + i * 256; int r = s >> 3, cc = s & 7;
                ra[i] = *reinterpret_cast<const float4*>(Ab + (size_t)r * HH + (k0 + 32) + cc * 4);
                rb[i] = *reinterpret_cast<const float4*>(Bb + (size_t)r * HH + (k0 + 32) + cc * 4);
            }
        }
#pragma unroll
        for (int kk = 0; kk < 32; kk++) {
            float4 av = *reinterpret_cast<const float4*>(As + kk * XAS + ty * 4);
            float4 bv = *reinterpret_cast<const float4*>(Bs + kk * XAS + tx * 4);
            float a4[4] = {av.x, av.y, av.z, av.w};
            float b4[4] = {bv.x, bv.y, bv.z, bv.w};
#pragma unroll
            for (int i = 0; i < 4; i++)
#pragma unroll
                for (int j = 0; j < 4; j++) acc[i][j] += a4[i] * b4[j];
        }
    }
    const int n = n0 + tx * 4;
    float b0 = bih[n + 0] + bhh[n + 0], b1 = bih[n + 1] + bhh[n + 1];
    float b2 = bih[n + 2] + bhh[n + 2], b3 = bih[n + 3] + bhh[n + 3];
#pragma unroll
    for (int i = 0; i < 4; i++) {
        float4 v = make_float4(acc[i][0] + b0, acc[i][1] + b1, acc[i][2] + b2, acc[i][3] + b3);
        *reinterpret_cast<float4*>(&g_xproj[(size_t)(m0 + ty * 4 + i) * GG + n]) = v;
    }
#endif
}

#define PAS 68
#define OFF_BS   0
#define OFF_AS   32768
#define OFF_RED  (32768 + 2*32*PAS)
#define OFF_GS   (OFF_RED + 2048)
#define OFF_CS   (OFF_GS + 2048)
#define S_SMEM_BYTES ((OFF_CS + 512) * 4)

__global__ __launch_bounds__(256) void lstm_persist_simt(
    const float* __restrict__ Whh, float* __restrict__ out)
{
#if !TC_OK
    extern __shared__ __align__(16) float smf[];
    float* Bs  = smf + OFF_BS;
    float* Red = smf + OFF_RED;
    float* Gs  = smf + OFF_GS;
    float* Cs  = smf + OFF_CS;
    const int tid = threadIdx.x, bk = blockIdx.x;

    for (int i = tid; i < 32 * 1024; i += 256) {
        int k = i & 1023, c = i >> 10;
        int row = (c >> 3) * HH + bk * 8 + (c & 7);
        Bs[k * 32 + c] = Whh[(size_t)row * HH + k];
    }
    for (int i = tid; i < 512; i += 256) {
        Cs[i] = 0.f;
        int b = i >> 3, jj = i & 7;
        g_h[0][b * HH + bk * 8 + jj] = 0.f;
    }
    grid_barrier();

    const int grp = tid >> 7, ltid = tid & 127;
    const int tm = ltid >> 3, tn = ltid & 7;
    float* As = smf + OFF_AS + grp * (32 * PAS);

    for (int t = 0; t < TT; ++t) {
        const float* hprev = g_h[t & 1];
        float acc[4][4];
#pragma unroll
        for (int i = 0; i < 4; i++)
#pragma unroll
            for (int j = 0; j < 4; j++) acc[i][j] = 0.f;
        for (int ch = 0; ch < 16; ++ch) {
            const int kbase = grp * 512 + ch * 32;
            __syncthreads();
#pragma unroll
            for (int i = 0; i < 4; i++) {
                int s = ltid + i * 128; int r = s >> 3, cc = s & 7;
                float4 v = *reinterpret_cast<const float4*>(hprev + (size_t)r * HH + kbase + cc * 4);
                As[(cc * 4 + 0) * PAS + r] = v.x; As[(cc * 4 + 1) * PAS + r] = v.y;
                As[(cc * 4 + 2) * PAS + r] = v.z; As[(cc * 4 + 3) * PAS + r] = v.w;
            }
            __syncthreads();
#pragma unroll
            for (int kk = 0; kk < 32; kk++) {
                float4 av = *reinterpret_cast<const float4*>(As + kk * PAS + tm * 4);
                float4 bv = *reinterpret_cast<const float4*>(Bs + (kbase + kk) * 32 + tn * 4);
                float a4[4] = {av.x, av.y, av.z, av.w};
                float b4[4] = {bv.x, bv.y, bv.z, bv.w};
#pragma unroll
                for (int i = 0; i < 4; i++)
#pragma unroll
                    for (int j = 0; j < 4; j++) acc[i][j] += a4[i] * b4[j];
            }
        }
        __syncthreads();
        if (grp == 1) {
#pragma unroll
            for (int i = 0; i < 4; i++)
                *reinterpret_cast<float4*>(Red + (tm * 4 + i) * 32 + tn * 4) =
                    make_float4(acc[i][0], acc[i][1], acc[i][2], acc[i][3]);
        }
        __syncthreads();
        if (grp == 0) {
            const int g = tn >> 1, jj0 = (tn & 1) * 4;
            const int gcol = g * HH + bk * 8 + jj0;
#pragma unroll
            for (int i = 0; i < 4; i++) {
                const int b = tm * 4 + i;
                float4 rv = *reinterpret_cast<const float4*>(Red + b * 32 + tn * 4);
                float4 xp = *reinterpret_cast<const float4*>(&g_xproj[(size_t)(t * BB + b) * GG + gcol]);
                float4 v = make_float4(acc[i][0] + rv.x + xp.x, acc[i][1] + rv.y + xp.y,
                                       acc[i][2] + rv.z + xp.z, acc[i][3] + rv.w + xp.w);
                *reinterpret_cast<float4*>(Gs + g * 512 + b * 8 + jj0) = v;
            }
        }
        __syncthreads();
        float* hnext = g_h[(t + 1) & 1];
        for (int p = tid; p < 512; p += 256) {
            int b = p >> 3, jj = p & 7;
            float gi = sigf(Gs[p]);
            float gf = sigf(Gs[512 + p]);
            float gg = tanhf(Gs[1024 + p]);
            float go = sigf(Gs[1536 + p]);
            float c = gf * Cs[p] + gi * gg;
            Cs[p] = c;
            float h = go * tanhf(c);
            int col = bk * 8 + jj;
            out[(size_t)t * BB * HH + b * HH + col] = h;
            hnext[b * HH + col] = h;
            if (t == TT - 1) {
                out[(size_t)TT * BB * HH + b * HH + col] = h;
                out[(size_t)TT * BB * HH + BB * HH + b * HH + col] = c;
            }
        }
        grid_barrier();
    }
#endif
}

// ---------------- kernel_launch ----------------
extern "C" void kernel_launch(void* const* d_in, const int* in_sizes, int n_in,
                              void* d_out, int out_size) {
    const float* x    = (const float*)d_in[0];
    const float* W_ih = (const float*)d_in[1];
    const float* W_hh = (const float*)d_in[2];
    const float* b_ih = (const float*)d_in[3];
    const float* b_hh = (const float*)d_in[4];
    float* out = (float*)d_out;
    (void)in_sizes; (void)n_in; (void)out_size;

    cudaFuncSetAttribute(xproj_tc, cudaFuncAttributeMaxDynamicSharedMemorySize, X_SMEM);
    cudaFuncSetAttribute(lstm_persist_tc, cudaFuncAttributeMaxDynamicSharedMemorySize, P_SMEM);
    cudaFuncSetAttribute(lstm_persist_simt, cudaFuncAttributeMaxDynamicSharedMemorySize, S_SMEM_BYTES);

    // Tensor-core path (bodies empty if this build lacks sm_103a features)
    conv_x<<<(TT * BB * HH / 4) / 256, 256>>>(x);
    conv_w<<<(GG * HH / 4) / 256, 256>>>(W_ih);
    dim3 xg(32, 512);
    xproj_tc<<<xg, 256, X_SMEM>>>(b_ih, b_hh);
    lstm_persist_tc<<<NCTA, 256, P_SMEM>>>(W_hh, out);

    // SIMT fallback path (bodies empty if tensor path is available)
    dim3 sg(GG / 64, (TT * BB) / 64);
    xproj_simt<<<sg, 256>>>(x, W_ih, b_ih, b_hh);
    lstm_persist_simt<<<NCTA, 256, S_SMEM_BYTES>>>(W_hh, out);
}

// round 13
// speedup vs baseline: 1.4863x; 1.4863x over previous
#include <cuda_runtime.h>
#include <cuda_bf16.h>
#include <math.h>
#include <stdint.h>

#define TT 512
#define BB 64
#define HH 1024
#define GG 4096
#define NCTA 128

#if defined(__CUDA_ARCH__) && (defined(__CUDA_ARCH_FEAT_SM103_ALL) || \
    defined(__CUDA_ARCH_FEAT_SM100_ALL) || \
    (defined(__CUDA_ARCH_FAMILY_SPECIFIC__) && __CUDA_ARCH_FAMILY_SPECIFIC__ >= 1000))
#define TC_OK 1
#else
#define TC_OK 0
#endif

// ---------------- device globals ----------------
__device__ __align__(16) float g_xproj[(size_t)TT * BB * GG];      // 512 MB
// pre-swizzled chunk-major tiles: [tile][chunk][16 KB = 128 rows x 128 B SW128]
__device__ __align__(128) char g_xA2[512][16][16384];              // 128 MB
__device__ __align__(128) char g_whi2[32][16][16384];              // 8 MB
__device__ __align__(128) char g_wlo2[32][16][16384];              // 8 MB
__device__ __align__(128) char g_hsplit2[2][16][16384];            // h dbl buf
__device__ __align__(16) float g_h[2][BB * HH];                    // SIMT fallback
__device__ unsigned g_bar_count = 0, g_bar_gen = 0;

__device__ __forceinline__ float sigf(float x) { return 1.f / (1.f + __expf(-x)); }
__device__ __forceinline__ void split2(float a, float b, unsigned& hu, unsigned& lu) {
    __nv_bfloat16 h0 = __float2bfloat16(a), h1 = __float2bfloat16(b);
    float l0 = a - __bfloat162float(h0), l1 = b - __bfloat162float(h1);
    hu = (unsigned)__bfloat16_as_ushort(h0) | ((unsigned)__bfloat16_as_ushort(h1) << 16);
    lu = (unsigned)__bfloat16_as_ushort(__float2bfloat16(l0)) |
         ((unsigned)__bfloat16_as_ushort(__float2bfloat16(l1)) << 16);
}
__device__ __forceinline__ void grid_barrier() {
    __threadfence();
    __syncthreads();
    if (threadIdx.x == 0) {
        unsigned target = *(volatile unsigned*)&g_bar_gen + 1u;
        unsigned old = atomicAdd(&g_bar_count, 1u);
        if (old == NCTA - 1u) { g_bar_count = 0u; __threadfence(); atomicExch(&g_bar_gen, target); }
        else { while ((int)(*(volatile unsigned*)&g_bar_gen - target) < 0) __nanosleep(32); }
        __threadfence();
    }
    __syncthreads();
}

// ---------------- PTX helpers ----------------
__device__ __forceinline__ uint32_t smem_u32(const void* p) {
    uint32_t a;
    asm("{ .reg .u64 t; cvta.to.shared.u64 t, %1; cvt.u32.u64 %0, t; }" : "=r"(a) : "l"(p));
    return a;
}
#define SWZ(o) ((o) ^ ((((uint32_t)(o)) >> 3) & 0x70))
__device__ __forceinline__ uint64_t make_desc(uint32_t a) {
    return ((2ull << 61) | (1ull << 46) | (64ull << 32) | (1ull << 16)) | (uint64_t)((a >> 4) & 0x3FFF);
}
__device__ __forceinline__ void mbar_init(uint32_t a, uint32_t n) {
    asm volatile("mbarrier.init.shared.b64 [%0], %1;" :: "r"(a), "r"(n) : "memory");
}
__device__ __forceinline__ void mbar_wait(uint32_t a, uint32_t ph) {
    asm volatile("{\n .reg .pred P;\nWL_%=:\n"
                 " mbarrier.try_wait.parity.acquire.cta.shared::cta.b64 P, [%0], %1, 0x989680;\n"
                 " @P bra WD_%=;\n bra WL_%=;\nWD_%=:\n}" :: "r"(a), "r"(ph) : "memory");
}
__device__ __forceinline__ void mbar_expect_tx(uint32_t a, uint32_t bytes) {
    asm volatile("mbarrier.arrive.expect_tx.shared.b64 _, [%0], %1;" :: "r"(a), "r"(bytes) : "memory");
}
__device__ __forceinline__ void bulk_g2s(uint32_t dst, const void* src, uint32_t bytes, uint32_t mbar) {
    asm volatile("cp.async.bulk.shared::cta.global.mbarrier::complete_tx::bytes [%0], [%1], %2, [%3];"
                 :: "r"(dst), "l"(src), "r"(bytes), "r"(mbar) : "memory");
}
#if TC_OK
__device__ __forceinline__ void mma_ss(uint32_t d, uint64_t ad, uint64_t bd, uint32_t idesc, uint32_t acc) {
    asm volatile("{\n .reg .pred p;\n setp.ne.u32 p, %5, 0;\n"
                 " tcgen05.mma.cta_group::1.kind::f16 [%0], %1, %2, %3, {%4,%4,%4,%4}, p;\n}"
                 :: "r"(d), "l"(ad), "l"(bd), "r"(idesc), "r"(0u), "r"(acc) : "memory");
}
__device__ __forceinline__ void tc_commit(uint32_t m) {
    asm volatile("tcgen05.commit.cta_group::1.mbarrier::arrive::one.shared::cluster.b64 [%0];" :: "r"(m) : "memory");
}
#define TC_ALLOC(slot, n)  asm volatile("tcgen05.alloc.cta_group::1.sync.aligned.shared::cta.b32 [%0], %1;" :: "r"(slot), "r"(n) : "memory")
#define TC_DEALLOC(t, n)   asm volatile("tcgen05.dealloc.cta_group::1.sync.aligned.b32 %0, %1;" :: "r"(t), "r"(n))
#define TC_RELINQ()        asm volatile("tcgen05.relinquish_alloc_permit.cta_group::1.sync.aligned;")
#define TC_FENCE_AFTER()   asm volatile("tcgen05.fence::after_thread_sync;" ::: "memory")
#define TC_WAIT_LD()       asm volatile("tcgen05.wait::ld.sync.aligned;" ::: "memory")
#define FENCE_ASYNC()      asm volatile("fence.proxy.async.shared::cta;" ::: "memory")
#define LDTM_X32(r, a) \
    asm volatile("tcgen05.ld.sync.aligned.32x32b.x32.b32 " \
        "{%0,%1,%2,%3,%4,%5,%6,%7,%8,%9,%10,%11,%12,%13,%14,%15," \
        "%16,%17,%18,%19,%20,%21,%22,%23,%24,%25,%26,%27,%28,%29,%30,%31}, [%32];" \
        : "=r"((r)[0]),"=r"((r)[1]),"=r"((r)[2]),"=r"((r)[3]),"=r"((r)[4]),"=r"((r)[5]),"=r"((r)[6]),"=r"((r)[7]), \
          "=r"((r)[8]),"=r"((r)[9]),"=r"((r)[10]),"=r"((r)[11]),"=r"((r)[12]),"=r"((r)[13]),"=r"((r)[14]),"=r"((r)[15]), \
          "=r"((r)[16]),"=r"((r)[17]),"=r"((r)[18]),"=r"((r)[19]),"=r"((r)[20]),"=r"((r)[21]),"=r"((r)[22]),"=r"((r)[23]), \
          "=r"((r)[24]),"=r"((r)[25]),"=r"((r)[26]),"=r"((r)[27]),"=r"((r)[28]),"=r"((r)[29]),"=r"((r)[30]),"=r"((r)[31]) \
        : "r"(a))
#endif

#define IDESC_N32  0x8080490u   // f32 acc, bf16 x bf16, K-major, M=128, N=32
#define IDESC_N128 0x8200490u   // same, N=128

// ---------------- conversion kernels (pre-swizzled chunk-major) ----------------
__global__ __launch_bounds__(256) void conv_x(const float* __restrict__ x) {
#if TC_OK
    size_t e = ((size_t)blockIdx.x * 256 + threadIdx.x) * 4;
    int m = (int)(e >> 10), k = (int)(e & 1023);
    float4 v = *reinterpret_cast<const float4*>(x + e);
    uint2 hu, lu;
    split2(v.x, v.y, hu.x, lu.x);
    split2(v.z, v.w, hu.y, lu.y);
    int mt = m >> 6, b = m & 63, c = k >> 6, kk = k & 63;
    *reinterpret_cast<uint2*>(&g_xA2[mt][c][SWZ((uint32_t)(b * 128 + kk * 2))])        = hu;
    *reinterpret_cast<uint2*>(&g_xA2[mt][c][SWZ((uint32_t)((64 + b) * 128 + kk * 2))]) = lu;
#endif
}
__global__ __launch_bounds__(256) void conv_w(const float* __restrict__ W) {
#if TC_OK
    size_t e = ((size_t)blockIdx.x * 256 + threadIdx.x) * 4;
    int m = (int)(e >> 10), k = (int)(e & 1023);
    float4 v = *reinterpret_cast<const float4*>(W + e);
    uint2 hu, lu;
    split2(v.x, v.y, hu.x, lu.x);
    split2(v.z, v.w, hu.y, lu.y);
    int nt = m >> 7, row = m & 127, c = k >> 6, kk = k & 63;
    uint32_t off = SWZ((uint32_t)(row * 128 + kk * 2));
    *reinterpret_cast<uint2*>(&g_whi2[nt][c][off]) = hu;
    *reinterpret_cast<uint2*>(&g_wlo2[nt][c][off]) = lu;
#endif
}

// ---------------- xproj: bulk dual-driver tcgen05 GEMM (proven R12) ----------------
#define X_RED  98304
#define X_BIAS 106752
#define X_MISC 107264   // tmem@0; mma mbars@16,24; load mbars@32,40; fin@48
#define X_SMEM 107328

__global__ __launch_bounds__(256, 2) void xproj_tc(const float* __restrict__ bih,
                                                   const float* __restrict__ bhh) {
#if TC_OK
    extern __shared__ __align__(16) char sm[];
    const uint32_t sb = smem_u32(sm);
    const int tid = threadIdx.x, wid = tid >> 5, lane = tid & 31;
    const int nt = blockIdx.x, mt = blockIdx.y;
    float* Red  = reinterpret_cast<float*>(sm + X_RED);
    float* Bias = reinterpret_cast<float*>(sm + X_BIAS);
    const uint32_t mb_mma  = sb + X_MISC + 16;
    const uint32_t mb_load = sb + X_MISC + 32;
    const uint32_t mb_fin  = sb + X_MISC + 48;

    if (wid == 0) { TC_ALLOC(sb + X_MISC, 128); TC_RELINQ(); }
    if (tid < 128) Bias[tid] = bih[nt * 128 + tid] + bhh[nt * 128 + tid];
    if (tid == 0) {
        mbar_init(mb_mma, 1);  mbar_init(mb_mma + 8, 1);
        mbar_init(mb_load, 1); mbar_init(mb_load + 8, 1);
        mbar_init(mb_fin, 1);
    }
    __syncthreads();
    uint32_t tmem;
    asm volatile("ld.shared.b32 %0, [%1];" : "=r"(tmem) : "r"(sb + X_MISC));

    if (tid == 128) {             // load driver
        int phm[2] = {0, 0};
        for (int c = 0; c < 16; c++) {
            const int buf = c & 1;
            if (c >= 2) { mbar_wait(mb_mma + buf * 8, phm[buf]); phm[buf] ^= 1; }
            mbar_expect_tx(mb_load + buf * 8, 49152);
            uint32_t d = sb + (uint32_t)buf * 49152;
            bulk_g2s(d,         g_xA2[mt][c],  16384, mb_load + buf * 8);
            bulk_g2s(d + 16384, g_whi2[nt][c], 16384, mb_load + buf * 8);
            bulk_g2s(d + 32768, g_wlo2[nt][c], 16384, mb_load + buf * 8);
        }
    } else if (tid == 0) {        // MMA driver
        int phl[2] = {0, 0};
        for (int c = 0; c < 16; c++) {
            const int buf = c & 1;
            mbar_wait(mb_load + buf * 8, phl[buf]); phl[buf] ^= 1;
            uint32_t d = sb + (uint32_t)buf * 49152;
            uint64_t ad = make_desc(d), dh = make_desc(d + 16384), dl = make_desc(d + 32768);
#pragma unroll
            for (int ks = 0; ks < 4; ks++) {
                mma_ss(tmem, ad + 2 * ks, dh + 2 * ks, IDESC_N128, !(c == 0 && ks == 0));
                mma_ss(tmem, ad + 2 * ks, dl + 2 * ks, IDESC_N128, 1);
            }
            tc_commit(mb_mma + buf * 8);
        }
        tc_commit(mb_fin);        // tracks ALL prior MMAs of this thread
        mbar_wait(mb_fin, 0);     // single flip: properly paced
    }
    __syncthreads();
    TC_FENCE_AFTER();

    for (int blk = 0; blk < 4; blk++) {
        uint32_t rr[32];
        if (wid < 4) {
            LDTM_X32(rr, tmem + blk * 32);
            TC_WAIT_LD();
            if (wid >= 2) {
                int b = (wid - 2) * 32 + lane;
#pragma unroll
                for (int c = 0; c < 32; c++) Red[b * 33 + c] = __uint_as_float(rr[c]);
            }
        }
        __syncthreads();
        if (wid < 2) {
            int b = wid * 32 + lane;
            float* dst = &g_xproj[(size_t)(mt * 64 + b) * GG + nt * 128 + blk * 32];
#pragma unroll
            for (int c = 0; c < 32; c += 4) {
                float4 v = make_float4(
                    __uint_as_float(rr[c + 0]) + Red[b * 33 + c + 0] + Bias[blk * 32 + c + 0],
                    __uint_as_float(rr[c + 1]) + Red[b * 33 + c + 1] + Bias[blk * 32 + c + 1],
                    __uint_as_float(rr[c + 2]) + Red[b * 33 + c + 2] + Bias[blk * 32 + c + 2],
                    __uint_as_float(rr[c + 3]) + Red[b * 33 + c + 3] + Bias[blk * 32 + c + 3]);
                *reinterpret_cast<float4*>(dst + c) = v;
            }
        }
        __syncthreads();
    }
    if (wid == 0) TC_DEALLOC(tmem, 128);
#endif
}

// ---------------- persistent recurrence: dual-driver pipeline (proven R11) ----
#define P_WHI  0                 // 65536
#define P_WLO  65536             // 65536
#define P_ABUF 131072            // 4 x 16384
#define P_RED  196608            // 8448
#define P_MISC 205056            // tmem@0; mma mbars@16+8i; load mbars@48+8i
#define P_SMEM 205152

__global__ __launch_bounds__(256) void lstm_persist_tc(const float* __restrict__ Whh,
                                                       float* __restrict__ out) {
#if TC_OK
    extern __shared__ __align__(16) char sm[];
    const uint32_t sb = smem_u32(sm);
    const int tid = threadIdx.x, wid = tid >> 5, lane = tid & 31;
    const int bk = blockIdx.x;
    float* Red = reinterpret_cast<float*>(sm + P_RED);
    const uint32_t mb_mma  = sb + P_MISC + 16;   // +8*buf
    const uint32_t mb_load = sb + P_MISC + 48;   // +8*buf

    // W_hh slice -> SMEM SW128 (hi/lo), chunk c at +c*4096 (32 K-rows x 128B)
    for (int i = tid; i < 8192; i += 256) {
        int e = i * 4, cc = e >> 10, k = e & 1023;
        float4 v = *reinterpret_cast<const float4*>(
            &Whh[(size_t)((cc >> 3) * HH + bk * 8 + (cc & 7)) * HH + k]);
        uint2 hu, lu;
        split2(v.x, v.y, hu.x, lu.x);
        split2(v.z, v.w, hu.y, lu.y);
        uint32_t off = (uint32_t)((k >> 6) * 4096 + (cc >> 3) * 1024 + (cc & 7) * 128 + (k & 63) * 2);
        *reinterpret_cast<uint2*>(sm + P_WHI + SWZ(off)) = hu;
        *reinterpret_cast<uint2*>(sm + P_WLO + SWZ(off)) = lu;
    }
    // Zero this CTA's column slice of h buffer 0 (pre-swizzled layout).
    if (tid < 128) {
        *reinterpret_cast<uint4*>(
            &g_hsplit2[0][bk >> 3][SWZ((uint32_t)tid * 128 + (bk & 7) * 16)]) =
            make_uint4(0, 0, 0, 0);
    }
    if (wid == 0) { TC_ALLOC(sb + P_MISC, 32); TC_RELINQ(); }
    if (tid == 0) {
#pragma unroll
        for (int i = 0; i < 4; i++) {
            mbar_init(mb_mma + i * 8, 1);    // tc_commit arrival
            mbar_init(mb_load + i * 8, 1);   // expect_tx arrival + tx bytes
        }
    }
    __syncthreads();
    FENCE_ASYNC();   // order generic-proxy W stores before async-proxy MMA reads
    uint32_t tmem;
    asm volatile("ld.shared.b32 %0, [%1];" : "=r"(tmem) : "r"(sb + P_MISC));
    grid_barrier();
    const unsigned base = *(volatile unsigned*)&g_bar_gen;

    float cr[8];
#pragma unroll
    for (int j = 0; j < 8; j++) cr[j] = 0.f;

    for (int t = 0; t < TT; ++t) {
        // --- warps 0-1: XP slice straight into registers ---
        float4 xpr[8];
        if (wid < 2) {
            int b = wid * 32 + lane;
            const float* xsrc = &g_xproj[((size_t)t * BB + b) * GG + bk * 8];
#pragma unroll
            for (int g = 0; g < 4; g++) {
                xpr[2 * g]     = *reinterpret_cast<const float4*>(xsrc + g * HH);
                xpr[2 * g + 1] = *reinterpret_cast<const float4*>(xsrc + g * HH + 4);
            }
        }

        // --- step gate: only the two drivers wait for h publication ---
        if (tid == 0 || tid == 128) {
            unsigned target = base + (unsigned)t;
            while ((int)(*(volatile unsigned*)&g_bar_gen - target) < 0) {}
        }

        // --- load driver (tid 128) ---
        if (tid == 128) {
            const char* asrc = g_hsplit2[t & 1][0];
#pragma unroll
            for (int c = 0; c < 16; c++) {
                const int buf = c & 3;
                if (c >= 4) mbar_wait(mb_mma + buf * 8, ((c >> 2) - 1) & 1);
                mbar_expect_tx(mb_load + buf * 8, 16384);
                bulk_g2s(sb + P_ABUF + buf * 16384, asrc + c * 16384, 16384,
                         mb_load + buf * 8);
            }
        }
        // --- MMA driver (tid 0) ---
        if (tid == 0) {
#pragma unroll
            for (int c = 0; c < 16; c++) {
                const int buf = c & 3;
                mbar_wait(mb_load + buf * 8, (c >> 2) & 1);
                uint64_t ad = make_desc(sb + P_ABUF + buf * 16384);
                uint64_t dh = make_desc(sb + P_WHI + c * 4096);
                uint64_t dl = make_desc(sb + P_WLO + c * 4096);
#pragma unroll
                for (int ks = 0; ks < 4; ks++) {
                    mma_ss(tmem, ad + 2 * ks, dh + 2 * ks, IDESC_N32, !(c == 0 && ks == 0));
                    mma_ss(tmem, ad + 2 * ks, dl + 2 * ks, IDESC_N32, 1);
                }
                tc_commit(mb_mma + buf * 8);
            }
            // drain: loader's 3rd-flip waits guarantee >=3 completions here,
            // so wait(1) blocks exactly until the 4th completion per buf.
#pragma unroll
            for (int i = 0; i < 4; i++) mbar_wait(mb_mma + i * 8, 1);
        }
        __syncthreads();
        TC_FENCE_AFTER();

        // --- epilogue: fold hi+lo, add xproj (regs), pointwise, store h ---
        uint32_t rr[32];
        if (wid < 4) {
            LDTM_X32(rr, tmem);
            TC_WAIT_LD();
            if (wid >= 2) {
                int b = (wid - 2) * 32 + lane;
#pragma unroll
                for (int c = 0; c < 32; c++) Red[b * 33 + c] = __uint_as_float(rr[c]);
            }
        }
        __syncthreads();
        if (wid < 2) {
            int b = wid * 32 + lane;
            const float* xpf = reinterpret_cast<const float*>(xpr);
            float gate[32];
#pragma unroll
            for (int c = 0; c < 32; c++)
                gate[c] = xpf[c] + __uint_as_float(rr[c]) + Red[b * 33 + c];

            float hs[8];
            __nv_bfloat16 hb[8], lb[8];
#pragma unroll
            for (int j = 0; j < 8; j++) {
                float iv = sigf(gate[j]);
                float fv = sigf(gate[8 + j]);
                float gv = tanhf(gate[16 + j]);
                float ov = sigf(gate[24 + j]);
                cr[j] = fv * cr[j] + iv * gv;
                hs[j] = ov * tanhf(cr[j]);
                hb[j] = __float2bfloat16(hs[j]);
                lb[j] = __float2bfloat16(hs[j] - __bfloat162float(hb[j]));
            }
            float* op = &out[((size_t)t * BB + b) * HH + bk * 8];
            *reinterpret_cast<float4*>(op)     = make_float4(hs[0], hs[1], hs[2], hs[3]);
            *reinterpret_cast<float4*>(op + 4) = make_float4(hs[4], hs[5], hs[6], hs[7]);
            int nsel = (t + 1) & 1;
            char* hcb = g_hsplit2[nsel][bk >> 3];
            *reinterpret_cast<uint4*>(&hcb[SWZ((uint32_t)b * 128 + (bk & 7) * 16)]) =
                *reinterpret_cast<uint4*>(hb);
            *reinterpret_cast<uint4*>(&hcb[SWZ((uint32_t)(64 + b) * 128 + (bk & 7) * 16)]) =
                *reinterpret_cast<uint4*>(lb);
            if (t == TT - 1) {
                float* hp = &out[(size_t)TT * BB * HH + (size_t)b * HH + bk * 8];
                *reinterpret_cast<float4*>(hp)     = make_float4(hs[0], hs[1], hs[2], hs[3]);
                *reinterpret_cast<float4*>(hp + 4) = make_float4(hs[4], hs[5], hs[6], hs[7]);
                float* cp = hp + (size_t)BB * HH;
                *reinterpret_cast<float4*>(cp)     = make_float4(cr[0], cr[1], cr[2], cr[3]);
                *reinterpret_cast<float4*>(cp + 4) = make_float4(cr[4], cr[5], cr[6], cr[7]);
            }
            // early arrival: h published for this CTA (warps 0-1 only)
            asm volatile("bar.sync 1, 64;" ::: "memory");
            if (tid == 0) {
                __threadfence();
                unsigned old = atomicAdd(&g_bar_count, 1u);
                if (old == NCTA - 1u) {
                    atomicExch(&g_bar_count, 0u);
                    __threadfence();
                    atomicExch(&g_bar_gen, base + (unsigned)t + 1u);
                }
            }
        }
    }
    __syncthreads();
    if (wid == 0) TC_DEALLOC(tmem, 32);
#endif
}

// ---------------- SIMT fallback (non-'a' pass only) ----------------
#define XAS 68
__global__ __launch_bounds__(256) void xproj_simt(
    const float* __restrict__ x, const float* __restrict__ Wih,
    const float* __restrict__ bih, const float* __restrict__ bhh)
{
#if !TC_OK
    __shared__ __align__(16) float As[32 * XAS];
    __shared__ __align__(16) float Bs[32 * XAS];
    const int tid = threadIdx.x;
    const int n0 = blockIdx.x * 64, m0 = blockIdx.y * 64;
    const int ty = tid >> 4, tx = tid & 15;
    const float* Ab = x   + (size_t)m0 * HH;
    const float* Bb = Wih + (size_t)n0 * HH;
    float acc[4][4];
#pragma unroll
    for (int i = 0; i < 4; i++)
#pragma unroll
        for (int j = 0; j < 4; j++) acc[i][j] = 0.f;
    float4 ra[2], rb[2];
#pragma unroll
    for (int i = 0; i < 2; i++) {
        int s = tid + i * 256; int r = s >> 3, cc = s & 7;
        ra[i] = *reinterpret_cast<const float4*>(Ab + (size_t)r * HH + cc * 4);
        rb[i] = *reinterpret_cast<const float4*>(Bb + (size_t)r * HH + cc * 4);
    }
    for (int k0 = 0; k0 < HH; k0 += 32) {
        __syncthreads();
#pragma unroll
        for (int i = 0; i < 2; i++) {
            int s = tid + i * 256; int r = s >> 3, cc = s & 7;
            As[(cc * 4 + 0) * XAS + r] = ra[i].x; As[(cc * 4 + 1) * XAS + r] = ra[i].y;
            As[(cc * 4 + 2) * XAS + r] = ra[i].z; As[(cc * 4 + 3) * XAS + r] = ra[i].w;
            Bs[(cc * 4 + 0) * XAS + r] = rb[i].x; Bs[(cc * 4 + 1) * XAS + r] = rb[i].y;
            Bs[(cc * 4 + 2) * XAS + r] = rb[i].z; Bs[(cc * 4 + 3) * XAS + r] = rb[i].w;
        }
        __syncthreads();
        if (k0 + 32 < HH) {
#pragma unroll
            for (int i = 0; i < 2; i++) {
                int s = tid + i * 256; int r = s >> 3, cc = s & 7;
                ra[i] = *reinterpret_cast<const float4*>(Ab + (size_t)r * HH + (k0 + 32) + cc * 4);
                rb[i] = *reinterpret_cast<const float4*>(Bb + (size_t)r * HH + (k0 + 32) + cc * 4);
            }
        }
#pragma unroll
        for (int kk = 0; kk < 32; kk++) {
            float4 av = *reinterpret_cast<const float4*>(As + kk * XAS + ty * 4);
            float4 bv = *reinterpret_cast<const float4*>(Bs + kk * XAS + tx * 4);
            float a4[4] = {av.x, av.y, av.z, av.w};
            float b4[4] = {bv.x, bv.y, bv.z, bv.w};
#pragma unroll
            for (int i = 0; i < 4; i++)
#pragma unroll
                for (int j = 0; j < 4; j++) acc[i][j] += a4[i] * b4[j];
        }
    }
    const int n = n0 + tx * 4;
    float b0 = bih[n + 0] + bhh[n + 0], b1 = bih[n + 1] + bhh[n + 1];
    float b2 = bih[n + 2] + bhh[n + 2], b3 = bih[n + 3] + bhh[n + 3];
#pragma unroll
    for (int i = 0; i < 4; i++) {
        float4 v = make_float4(acc[i][0] + b0, acc[i][1] + b1, acc[i][2] + b2, acc[i][3] + b3);
        *reinterpret_cast<float4*>(&g_xproj[(size_t)(m0 + ty * 4 + i) * GG + n]) = v;
    }
#endif
}

#define PAS 68
#define OFF_BS   0
#define OFF_AS   32768
#define OFF_RED  (32768 + 2*32*PAS)
#define OFF_GS   (OFF_RED + 2048)
#define OFF_CS   (OFF_GS + 2048)
#define S_SMEM_BYTES ((OFF_CS + 512) * 4)

__global__ __launch_bounds__(256) void lstm_persist_simt(
    const float* __restrict__ Whh, float* __restrict__ out)
{
#if !TC_OK
    extern __shared__ __align__(16) float smf[];
    float* Bs  = smf + OFF_BS;
    float* Red = smf + OFF_RED;
    float* Gs  = smf + OFF_GS;
    float* Cs  = smf + OFF_CS;
    const int tid = threadIdx.x, bk = blockIdx.x;

    for (int i = tid; i < 32 * 1024; i += 256) {
        int k = i & 1023, c = i >> 10;
        int row = (c >> 3) * HH + bk * 8 + (c & 7);
        Bs[k * 32 + c] = Whh[(size_t)row * HH + k];
    }
    for (int i = tid; i < 512; i += 256) {
        Cs[i] = 0.f;
        int b = i >> 3, jj = i & 7;
        g_h[0][b * HH + bk * 8 + jj] = 0.f;
    }
    grid_barrier();

    const int grp = tid >> 7, ltid = tid & 127;
    const int tm = ltid >> 3, tn = ltid & 7;
    float* As = smf + OFF_AS + grp * (32 * PAS);

    for (int t = 0; t < TT; ++t) {
        const float* hprev = g_h[t & 1];
        float acc[4][4];
#pragma unroll
        for (int i = 0; i < 4; i++)
#pragma unroll
            for (int j = 0; j < 4; j++) acc[i][j] = 0.f;
        for (int ch = 0; ch < 16; ++ch) {
            const int kbase = grp * 512 + ch * 32;
            __syncthreads();
#pragma unroll
            for (int i = 0; i < 4; i++) {
                int s = ltid + i * 128; int r = s >> 3, cc = s & 7;
                float4 v = *reinterpret_cast<const float4*>(hprev + (size_t)r * HH + kbase + cc * 4);
                As[(cc * 4 + 0) * PAS + r] = v.x; As[(cc * 4 + 1) * PAS + r] = v.y;
                As[(cc * 4 + 2) * PAS + r] = v.z; As[(cc * 4 + 3) * PAS + r] = v.w;
            }
            __syncthreads();
#pragma unroll
            for (int kk = 0; kk < 32; kk++) {
                float4 av = *reinterpret_cast<const float4*>(As + kk * PAS + tm * 4);
                float4 bv = *reinterpret_cast<const float4*>(Bs + (kbase + kk) * 32 + tn * 4);
                float a4[4] = {av.x, av.y, av.z, av.w};
                float b4[4] = {bv.x, bv.y, bv.z, bv.w};
#pragma unroll
                for (int i = 0; i < 4; i++)
#pragma unroll
                    for (int j = 0; j < 4; j++) acc[i][j] += a4[i] * b4[j];
            }
        }
        __syncthreads();
        if (grp == 1) {
#pragma unroll
            for (int i = 0; i < 4; i++)
                *reinterpret_cast<float4*>(Red + (tm * 4 + i) * 32 + tn * 4) =
                    make_float4(acc[i][0], acc[i][1], acc[i][2], acc[i][3]);
        }
        __syncthreads();
        if (grp == 0) {
            const int g = tn >> 1, jj0 = (tn & 1) * 4;
            const int gcol = g * HH + bk * 8 + jj0;
#pragma unroll
            for (int i = 0; i < 4; i++) {
                const int b = tm * 4 + i;
                float4 rv = *reinterpret_cast<const float4*>(Red + b * 32 + tn * 4);
                float4 xp = *reinterpret_cast<const float4*>(&g_xproj[(size_t)(t * BB + b) * GG + gcol]);
                float4 v = make_float4(acc[i][0] + rv.x + xp.x, acc[i][1] + rv.y + xp.y,
                                       acc[i][2] + rv.z + xp.z, acc[i][3] + rv.w + xp.w);
                *reinterpret_cast<float4*>(Gs + g * 512 + b * 8 + jj0) = v;
            }
        }
        __syncthreads();
        float* hnext = g_h[(t + 1) & 1];
        for (int p = tid; p < 512; p += 256) {
            int b = p >> 3, jj = p & 7;
            float gi = sigf(Gs[p]);
            float gf = sigf(Gs[512 + p]);
            float gg = tanhf(Gs[1024 + p]);
            float go = sigf(Gs[1536 + p]);
            float c = gf * Cs[p] + gi * gg;
            Cs[p] = c;
            float h = go * tanhf(c);
            int col = bk * 8 + jj;
            out[(size_t)t * BB * HH + b * HH + col] = h;
            hnext[b * HH + col] = h;
            if (t == TT - 1) {
                out[(size_t)TT * BB * HH + b * HH + col] = h;
                out[(size_t)TT * BB * HH + BB * HH + b * HH + col] = c;
            }
        }
        grid_barrier();
    }
#endif
}

// ---------------- kernel_launch ----------------
extern "C" void kernel_launch(void* const* d_in, const int* in_sizes, int n_in,
                              void* d_out, int out_size) {
    const float* x    = (const float*)d_in[0];
    const float* W_ih = (const float*)d_in[1];
    const float* W_hh = (const float*)d_in[2];
    const float* b_ih = (const float*)d_in[3];
    const float* b_hh = (const float*)d_in[4];
    float* out = (float*)d_out;
    (void)in_sizes; (void)n_in; (void)out_size;

    cudaFuncSetAttribute(xproj_tc, cudaFuncAttributeMaxDynamicSharedMemorySize, X_SMEM);
    cudaFuncSetAttribute(lstm_persist_tc, cudaFuncAttributeMaxDynamicSharedMemorySize, P_SMEM);
    cudaFuncSetAttribute(lstm_persist_simt, cudaFuncAttributeMaxDynamicSharedMemorySize, S_SMEM_BYTES);

    // Tensor-core path (bodies empty if this build lacks sm_103a features)
    conv_x<<<(TT * BB * HH / 4) / 256, 256>>>(x);
    conv_w<<<(GG * HH / 4) / 256, 256>>>(W_ih);
    dim3 xg(32, 512);
    xproj_tc<<<xg, 256, X_SMEM>>>(b_ih, b_hh);
    lstm_persist_tc<<<NCTA, 256, P_SMEM>>>(W_hh, out);

    // SIMT fallback path (bodies empty if tensor path is available)
    dim3 sg(GG / 64, (TT * BB) / 64);
    xproj_simt<<<sg, 256>>>(x, W_ih, b_ih, b_hh);
    lstm_persist_simt<<<NCTA, 256, S_SMEM_BYTES>>>(W_hh, out);
}